// round 5
// baseline (speedup 1.0000x reference)
#include <cuda_runtime.h>
#include <cstdint>

// Problem constants
constexpr int B_  = 32;
constexpr int T_  = 1024;
constexpr int F_  = 512;
constexpr int H_  = 512;
constexpr int G4H = 2048;   // 4*H

#define NB 128   // recurrence blocks (<=148 SMs -> co-resident, grid barrier safe)
#define NT 256   // threads per block (8 warps -> 2 per SMSP)

// ---------------- device scratch ----------------
__device__ float g_z0t[(size_t)T_ * G4H * B_];   // [t][gatecol][b]
__device__ float g_hT[2][H_ * B_];               // ping-pong h, transposed [k][b]
// Monotonic hierarchical barrier state (reset by gemm block (0,0) each call).
__device__ unsigned g_grp[16 * 32];              // 16 counters, 128B apart
__device__ unsigned g_root;
__device__ volatile unsigned g_sense;            // monotonic: steps released

// ---------------- f32x2 helpers ----------------
__device__ __forceinline__ unsigned long long pack2(float x, float y) {
    unsigned long long r;
    asm("mov.b64 %0, {%1, %2};" : "=l"(r) : "f"(x), "f"(y));
    return r;
}
__device__ __forceinline__ unsigned long long fma2(unsigned long long a,
                                                   unsigned long long b,
                                                   unsigned long long c) {
    unsigned long long d;
    asm("fma.rn.f32x2 %0, %1, %2, %3;" : "=l"(d) : "l"(a), "l"(b), "l"(c));
    return d;
}
__device__ __forceinline__ unsigned long long add2(unsigned long long a,
                                                   unsigned long long b) {
    unsigned long long d;
    asm("add.rn.f32x2 %0, %1, %2;" : "=l"(d) : "l"(a), "l"(b));
    return d;
}
__device__ __forceinline__ float2 unpack2(unsigned long long v) {
    float2 f;
    asm("mov.b64 {%0, %1}, %2;" : "=f"(f.x), "=f"(f.y) : "l"(v));
    return f;
}

// ---------------- GEMM (f32x2) + embedded init ----------------
// z0t[t][col][b] = x[b,t,:] @ Wi[:,col] + bias[col]
// M = B*T = 32768, K = 512, N = 2048. 64x64 tile, BK=16, 256 threads.
__global__ void __launch_bounds__(256) gemm_xwi(const float* __restrict__ x,
                                                const float* __restrict__ Wi,
                                                const float* __restrict__ bias,
                                                const float* __restrict__ h0) {
    __shared__ float As[16][64];
    __shared__ float Bs[16][64];
    const int tid = threadIdx.x;

    if (blockIdx.x == 0 && blockIdx.y == 0) {
        for (int i = tid; i < H_ * B_; i += 256) {
            int b = i / H_;
            int k = i - b * H_;
            g_hT[0][k * B_ + b] = h0[i];
        }
        if (tid < 16) g_grp[tid * 32] = 0;
        if (tid == 0) { g_root = 0; g_sense = 0; }
    }

    const int tm = tid >> 4;
    const int tn = tid & 15;
    const int row0 = blockIdx.y * 64;
    const int col0 = blockIdx.x * 64;

    unsigned long long acc[4][2] = {};

    const int ar  = tid >> 2;
    const int akq = (tid & 3) * 4;
    const int br  = tid >> 4;
    const int bnq = (tid & 15) * 4;

    for (int kt = 0; kt < F_; kt += 16) {
        float4 av = *(const float4*)&x[(size_t)(row0 + ar) * F_ + kt + akq];
        As[akq + 0][ar] = av.x;
        As[akq + 1][ar] = av.y;
        As[akq + 2][ar] = av.z;
        As[akq + 3][ar] = av.w;
        *(float4*)&Bs[br][bnq] =
            *(const float4*)&Wi[(size_t)(kt + br) * G4H + col0 + bnq];
        __syncthreads();
#pragma unroll
        for (int k = 0; k < 16; k++) {
            float4 a = *(const float4*)&As[k][tm * 4];
            const unsigned long long* bp =
                (const unsigned long long*)&Bs[k][tn * 4];
            unsigned long long b0 = bp[0], b1 = bp[1];
            unsigned long long a0 = pack2(a.x, a.x);
            unsigned long long a1 = pack2(a.y, a.y);
            unsigned long long a2 = pack2(a.z, a.z);
            unsigned long long a3 = pack2(a.w, a.w);
            acc[0][0] = fma2(a0, b0, acc[0][0]); acc[0][1] = fma2(a0, b1, acc[0][1]);
            acc[1][0] = fma2(a1, b0, acc[1][0]); acc[1][1] = fma2(a1, b1, acc[1][1]);
            acc[2][0] = fma2(a2, b0, acc[2][0]); acc[2][1] = fma2(a2, b1, acc[2][1]);
            acc[3][0] = fma2(a3, b0, acc[3][0]); acc[3][1] = fma2(a3, b1, acc[3][1]);
        }
        __syncthreads();
    }

#pragma unroll
    for (int i = 0; i < 4; i++) {
        int r  = row0 + tm * 4 + i;
        int t  = r & (T_ - 1);
        int bb = r >> 10;
#pragma unroll
        for (int j = 0; j < 2; j++) {
            float2 v = unpack2(acc[i][j]);
            int c0c = col0 + tn * 4 + j * 2;
            g_z0t[((size_t)t * G4H + c0c + 0) * B_ + bb] = v.x + bias[c0c + 0];
            g_z0t[((size_t)t * G4H + c0c + 1) * B_ + bb] = v.y + bias[c0c + 1];
        }
    }
}

// ---------------- recurrence ----------------
// Block bx owns h columns [bx*4, bx*4+4).
// Thread: b = tid&31, nl = (tid>>5)&3, half = tid>>7 (split-K over 256 k each).
// Dynamic smem:
//   Whs2[H*8]     u64  32KB   (wi,wf),(wg,wo) pairs per (k, nl)
//   hdup[H*32]    u64 128KB   (h,h) duplicated pairs, [k][b]
//   red [128]     ulonglong2 2KB  split-K reduction buffer
__global__ void __launch_bounds__(NT, 1) lstm_rec(const float* __restrict__ c0,
                                                  const float* __restrict__ Wh,
                                                  float* __restrict__ out) {
    extern __shared__ unsigned char dsm[];
    unsigned long long* Whs2 = (unsigned long long*)dsm;       // [k*8 + nl*2]
    unsigned long long* hdup = Whs2 + H_ * 8;                  // [k*32 + b]
    ulonglong2* red = (ulonglong2*)(hdup + H_ * 32);           // [128]

    const int tid  = threadIdx.x;
    const int b    = tid & 31;
    const int nl   = (tid >> 5) & 3;
    const int half = tid >> 7;                   // 0 or 1
    const int ncol = blockIdx.x * 4 + nl;
    const int lo   = tid & 127;

    // Stage Wh slice once: (wi,wf) and (wg,wo) f32x2 pairs per (k, nl).
    for (int idx = tid; idx < H_ * 4; idx += NT) {
        int k  = idx >> 2;
        int n2 = idx & 3;
        int cb = blockIdx.x * 4 + n2;
        float wi = Wh[(size_t)k * G4H + 0 * H_ + cb];
        float wf = Wh[(size_t)k * G4H + 1 * H_ + cb];
        float wg = Wh[(size_t)k * G4H + 2 * H_ + cb];
        float wo = Wh[(size_t)k * G4H + 3 * H_ + cb];
        Whs2[k * 8 + n2 * 2 + 0] = pack2(wi, wf);
        Whs2[k * 8 + n2 * 2 + 1] = pack2(wg, wo);
    }

    float c = (half == 0) ? c0[(size_t)b * H_ + ncol] : 0.f;

    float* c_fin = out;
    float* h_fin = out + B_ * H_;
    float* hist  = out + 2 * B_ * H_;            // [b][t][h]

    const unsigned long long* Wp = Whs2 + (size_t)half * 256 * 8 + nl * 2;
    const unsigned long long* Hp = hdup + (size_t)half * 256 * 32 + b;
    const int rot = (blockIdx.x * 5) & 15;       // stagger L2 hotspot
    const int grp = blockIdx.x >> 3;             // 16 groups of 8 blocks

    __syncthreads();

    for (int t = 0; t < T_; t++) {
        const float4* __restrict__ hsrc4 = (const float4*)g_hT[t & 1];
        float* hdst = g_hT[(t + 1) & 1];

        // ---- z prefetch (lower half only; overlaps the stage) ----
        float z0 = 0.f, z1 = 0.f, z2 = 0.f, z3 = 0.f;
        if (half == 0) {
            size_t zbase = ((size_t)t * G4H + ncol) * B_ + b;
            z0 = __ldcs(&g_z0t[zbase + (size_t)0 * H_ * B_]);
            z1 = __ldcs(&g_z0t[zbase + (size_t)1 * H_ * B_]);
            z2 = __ldcs(&g_z0t[zbase + (size_t)2 * H_ * B_]);
            z3 = __ldcs(&g_z0t[zbase + (size_t)3 * H_ * B_]);
        }

        // ---- stage h: 16 float4/thread via ld.global.cg -> duplicated pairs ----
        // float4 index i covers k = i>>3, b0 = (4*i)&31 -> hdup[k*32 + b0 .. +3].
#pragma unroll
        for (int cch = 0; cch < 2; cch++) {
            int j0 = ((cch * 8 + 0) + rot) & 15;
            int j1 = ((cch * 8 + 1) + rot) & 15;
            int j2 = ((cch * 8 + 2) + rot) & 15;
            int j3 = ((cch * 8 + 3) + rot) & 15;
            int j4 = ((cch * 8 + 4) + rot) & 15;
            int j5 = ((cch * 8 + 5) + rot) & 15;
            int j6 = ((cch * 8 + 6) + rot) & 15;
            int j7 = ((cch * 8 + 7) + rot) & 15;
            float4 r0 = __ldcg(&hsrc4[tid + NT * j0]);
            float4 r1 = __ldcg(&hsrc4[tid + NT * j1]);
            float4 r2 = __ldcg(&hsrc4[tid + NT * j2]);
            float4 r3 = __ldcg(&hsrc4[tid + NT * j3]);
            float4 r4 = __ldcg(&hsrc4[tid + NT * j4]);
            float4 r5 = __ldcg(&hsrc4[tid + NT * j5]);
            float4 r6 = __ldcg(&hsrc4[tid + NT * j6]);
            float4 r7 = __ldcg(&hsrc4[tid + NT * j7]);
#define DUP_STORE(rr, jj)                                                     \
            {                                                                 \
                int i4 = tid + NT * (jj);                                     \
                ulonglong2* d = (ulonglong2*)(hdup + (size_t)i4 * 4);         \
                d[0] = make_ulonglong2(pack2(rr.x, rr.x), pack2(rr.y, rr.y)); \
                d[1] = make_ulonglong2(pack2(rr.z, rr.z), pack2(rr.w, rr.w)); \
            }
            DUP_STORE(r0, j0) DUP_STORE(r1, j1) DUP_STORE(r2, j2)
            DUP_STORE(r3, j3) DUP_STORE(r4, j4) DUP_STORE(r5, j5)
            DUP_STORE(r6, j6) DUP_STORE(r7, j7)
#undef DUP_STORE
        }
        __syncthreads();

        // ---- gate pre-activations: this thread covers 256 k values ----
        unsigned long long aif0 = pack2(z0, z1), aif1 = 0;
        unsigned long long ago0 = pack2(z2, z3), ago1 = 0;
#pragma unroll 8
        for (int k = 0; k < 256; k += 2) {
            unsigned long long hh0 = Hp[(size_t)(k + 0) * 32];   // LDS.64
            unsigned long long hh1 = Hp[(size_t)(k + 1) * 32];
            ulonglong2 w0 = *(const ulonglong2*)(Wp + (size_t)(k + 0) * 8);
            ulonglong2 w1 = *(const ulonglong2*)(Wp + (size_t)(k + 1) * 8);
            aif0 = fma2(hh0, w0.x, aif0);
            ago0 = fma2(hh0, w0.y, ago0);
            aif1 = fma2(hh1, w1.x, aif1);
            ago1 = fma2(hh1, w1.y, ago1);
        }
        unsigned long long aif = add2(aif0, aif1);
        unsigned long long ago = add2(ago0, ago1);

        // ---- split-K reduction: upper half publishes, lower half combines ----
        if (half == 1) red[lo] = make_ulonglong2(aif, ago);
        __syncthreads();

        if (half == 0) {
            ulonglong2 other = red[lo];
            float2 zif = unpack2(add2(aif, other.x));
            float2 zgo = unpack2(add2(ago, other.y));

            float ig = 1.f / (1.f + __expf(-zif.x));
            float fg = 1.f / (1.f + __expf(-zif.y));
            float gg = tanhf(zgo.x);
            float og = 1.f / (1.f + __expf(-zgo.y));
            c = fg * c + ig * gg;
            float h = og * tanhf(c);

            __stcg(&hdst[ncol * B_ + b], h);               // publish via L2
            hist[((size_t)b * T_ + t) * H_ + ncol] = h;

            if (t == T_ - 1) {
                c_fin[b * H_ + ncol] = c;
                h_fin[b * H_ + ncol] = h;
            }
        }

        // ---- monotonic hierarchical grid barrier ----
        __threadfence();              // order h publish before arrive
        __syncthreads();              // all lanes done with hdup/red, too
        if (tid == 0) {
            unsigned target = (unsigned)(t + 1);
            unsigned old = atomicAdd(&g_grp[grp * 32], 1);
            if (old == 8u * target - 1u) {
                unsigned r = atomicAdd(&g_root, 1);
                if (r == 16u * target - 1u) g_sense = target;
            }
            while (g_sense < target) { }
        }
        __syncthreads();
        // no consumer threadfence: all cross-step reads bypass L1 (.cg/.volatile)
    }
}

// ---------------- launch ----------------
extern "C" void kernel_launch(void* const* d_in, const int* in_sizes, int n_in,
                              void* d_out, int out_size) {
    const float* x    = (const float*)d_in[0];
    const float* h0   = (const float*)d_in[1];
    const float* c0   = (const float*)d_in[2];
    const float* Wi   = (const float*)d_in[3];
    const float* Wh   = (const float*)d_in[4];
    const float* bias = (const float*)d_in[5];
    float* out = (float*)d_out;

    // 32KB (Whs2) + 128KB (hdup) + 2KB (red) = 163840 bytes
    const int rec_smem = H_ * 8 * 8 + H_ * 32 * 8 + 128 * 16;
    cudaFuncSetAttribute(lstm_rec, cudaFuncAttributeMaxDynamicSharedMemorySize,
                         rec_smem);

    dim3 ggrid(G4H / 64, (B_ * T_) / 64);
    gemm_xwi<<<ggrid, 256>>>(x, Wi, bias, h0);

    lstm_rec<<<NB, NT, rec_smem>>>(c0, Wh, out);
}

// round 6
// speedup vs baseline: 1.3109x; 1.3109x over previous
#include <cuda_runtime.h>
#include <cstdint>

// Problem constants
constexpr int B_  = 32;
constexpr int T_  = 1024;
constexpr int F_  = 512;
constexpr int H_  = 512;
constexpr int G4H = 2048;   // 4*H

#define NB 128   // recurrence blocks (<=148 SMs -> co-resident, grid barrier safe)
#define NT 256   // 8 warps: warp w owns k-slice [64w, 64w+64)
#define KW 64    // k per warp

// ---------------- device scratch ----------------
__device__ float g_z0t[(size_t)T_ * G4H * B_];   // [t][gatecol][b]
__device__ float g_hT[2][H_ * B_];               // ping-pong h, transposed [k][b]
// Monotonic hierarchical barrier state (reset by gemm block (0,0) each call).
__device__ unsigned g_grp[16 * 32];              // 16 counters, 128B apart
__device__ unsigned g_root;
__device__ volatile unsigned g_sense;            // monotonic: steps released

// ---------------- f32x2 helpers ----------------
__device__ __forceinline__ unsigned long long pack2(float x, float y) {
    unsigned long long r;
    asm("mov.b64 %0, {%1, %2};" : "=l"(r) : "f"(x), "f"(y));
    return r;
}
__device__ __forceinline__ unsigned long long fma2(unsigned long long a,
                                                   unsigned long long b,
                                                   unsigned long long c) {
    unsigned long long d;
    asm("fma.rn.f32x2 %0, %1, %2, %3;" : "=l"(d) : "l"(a), "l"(b), "l"(c));
    return d;
}
__device__ __forceinline__ unsigned long long add2(unsigned long long a,
                                                   unsigned long long b) {
    unsigned long long d;
    asm("add.rn.f32x2 %0, %1, %2;" : "=l"(d) : "l"(a), "l"(b));
    return d;
}
__device__ __forceinline__ float2 unpack2(unsigned long long v) {
    float2 f;
    asm("mov.b64 {%0, %1}, %2;" : "=f"(f.x), "=f"(f.y) : "l"(v));
    return f;
}

// ---------------- GEMM (f32x2) + embedded init (validated) ----------------
__global__ void __launch_bounds__(256) gemm_xwi(const float* __restrict__ x,
                                                const float* __restrict__ Wi,
                                                const float* __restrict__ bias,
                                                const float* __restrict__ h0) {
    __shared__ float As[16][64];
    __shared__ float Bs[16][64];
    const int tid = threadIdx.x;

    if (blockIdx.x == 0 && blockIdx.y == 0) {
        for (int i = tid; i < H_ * B_; i += 256) {
            int b = i / H_;
            int k = i - b * H_;
            g_hT[0][k * B_ + b] = h0[i];
        }
        if (tid < 16) g_grp[tid * 32] = 0;
        if (tid == 0) { g_root = 0; g_sense = 0; }
    }

    const int tm = tid >> 4;
    const int tn = tid & 15;
    const int row0 = blockIdx.y * 64;
    const int col0 = blockIdx.x * 64;

    unsigned long long acc[4][2] = {};

    const int ar  = tid >> 2;
    const int akq = (tid & 3) * 4;
    const int br  = tid >> 4;
    const int bnq = (tid & 15) * 4;

    for (int kt = 0; kt < F_; kt += 16) {
        float4 av = *(const float4*)&x[(size_t)(row0 + ar) * F_ + kt + akq];
        As[akq + 0][ar] = av.x;
        As[akq + 1][ar] = av.y;
        As[akq + 2][ar] = av.z;
        As[akq + 3][ar] = av.w;
        *(float4*)&Bs[br][bnq] =
            *(const float4*)&Wi[(size_t)(kt + br) * G4H + col0 + bnq];
        __syncthreads();
#pragma unroll
        for (int k = 0; k < 16; k++) {
            float4 a = *(const float4*)&As[k][tm * 4];
            const unsigned long long* bp =
                (const unsigned long long*)&Bs[k][tn * 4];
            unsigned long long b0 = bp[0], b1 = bp[1];
            unsigned long long a0 = pack2(a.x, a.x);
            unsigned long long a1 = pack2(a.y, a.y);
            unsigned long long a2 = pack2(a.z, a.z);
            unsigned long long a3 = pack2(a.w, a.w);
            acc[0][0] = fma2(a0, b0, acc[0][0]); acc[0][1] = fma2(a0, b1, acc[0][1]);
            acc[1][0] = fma2(a1, b0, acc[1][0]); acc[1][1] = fma2(a1, b1, acc[1][1]);
            acc[2][0] = fma2(a2, b0, acc[2][0]); acc[2][1] = fma2(a2, b1, acc[2][1]);
            acc[3][0] = fma2(a3, b0, acc[3][0]); acc[3][1] = fma2(a3, b1, acc[3][1]);
        }
        __syncthreads();
    }

#pragma unroll
    for (int i = 0; i < 4; i++) {
        int r  = row0 + tm * 4 + i;
        int t  = r & (T_ - 1);
        int bb = r >> 10;
#pragma unroll
        for (int j = 0; j < 2; j++) {
            float2 v = unpack2(acc[i][j]);
            int c0c = col0 + tn * 4 + j * 2;
            g_z0t[((size_t)t * G4H + c0c + 0) * B_ + bb] = v.x + bias[c0c + 0];
            g_z0t[((size_t)t * G4H + c0c + 1) * B_ + bb] = v.y + bias[c0c + 1];
        }
    }
}

// ---------------- recurrence ----------------
// Block bx owns h columns [bx*4, bx*4+4).
// Compute mapping: warp w = tid>>5 owns k in [64w,64w+64); lane = batch b.
// Each thread: 8 f32x2 accumulators = (i,f),(g,o) for 4 cols, its (b, k-slice).
// Epilogue mapping (tid<128): warp = nl (column), lane = b.
// Dynamic smem:
//   Wsu[512*8] u64  32KB : per k, [(wi,wf),(wg,wo)] x 4 cols
//   hs [512*32] f32 64KB : h state [k][b]
//   red[8*8*32] u64 16KB : red[j][w][b] split-k partials
//   hout[32*4]  f32 .5KB : h transpose buffer for coalesced hist store
__global__ void __launch_bounds__(NT, 1) lstm_rec(const float* __restrict__ c0,
                                                  const float* __restrict__ Wh,
                                                  float* __restrict__ out) {
    extern __shared__ unsigned char dsm[];
    unsigned long long* Wsu = (unsigned long long*)dsm;          // [k*8 + nl*2]
    float* hs = (float*)(Wsu + 512 * 8);                         // [k*32 + b]
    unsigned long long* red = (unsigned long long*)(hs + 512*32);// [j*256+w*32+b]
    float* hout = (float*)(red + 8 * 8 * 32);                    // [b*4 + nl]

    const int tid = threadIdx.x;
    const int w   = tid >> 5;
    const int b   = tid & 31;

    // Stage Wh slice once: (wi,wf),(wg,wo) pairs per (k, col nl).
    for (int idx = tid; idx < H_ * 4; idx += NT) {
        int k  = idx >> 2;
        int n2 = idx & 3;
        int cb = blockIdx.x * 4 + n2;
        float wi = Wh[(size_t)k * G4H + 0 * H_ + cb];
        float wf = Wh[(size_t)k * G4H + 1 * H_ + cb];
        float wg = Wh[(size_t)k * G4H + 2 * H_ + cb];
        float wo = Wh[(size_t)k * G4H + 3 * H_ + cb];
        Wsu[k * 8 + n2 * 2 + 0] = pack2(wi, wf);
        Wsu[k * 8 + n2 * 2 + 1] = pack2(wg, wo);
    }

    // Epilogue-mapped state (tid < 128): nl = tid>>5, bb = tid&31.
    const int nl = tid >> 5;
    const int bb = tid & 31;
    const int ncol = blockIdx.x * 4 + nl;
    float c = (tid < 128) ? c0[(size_t)bb * H_ + ncol] : 0.f;

    float* c_fin = out;
    float* h_fin = out + B_ * H_;
    float* hist  = out + 2 * B_ * H_;            // [b][t][h]

    const int grp = blockIdx.x >> 3;             // 16 groups of 8 blocks

    __syncthreads();

    for (int t = 0; t < T_; t++) {
        const float4* __restrict__ hsrc4 = (const float4*)g_hT[t & 1];
        float* hdst = g_hT[(t + 1) & 1];
        float4* hsf4 = (float4*)hs;

        // ---- z prefetch (epilogue threads; overlaps stage + compute) ----
        float z0 = 0.f, z1 = 0.f, z2 = 0.f, z3 = 0.f;
        if (tid < 128) {
            size_t zb = ((size_t)t * G4H + ncol) * B_ + bb;
            z0 = __ldcs(&g_z0t[zb + (size_t)0 * H_ * B_]);
            z1 = __ldcs(&g_z0t[zb + (size_t)1 * H_ * B_]);
            z2 = __ldcs(&g_z0t[zb + (size_t)2 * H_ * B_]);
            z3 = __ldcs(&g_z0t[zb + (size_t)3 * H_ * B_]);
        }

        // ---- warp-local stage: this warp's 8KB k-slice (512 float4/warp) ----
        {
            const int base = w * 512;
#pragma unroll
            for (int i = 0; i < 16; i += 4) {
                int j0 = base + (i + 0) * 32 + b;
                int j1 = base + (i + 1) * 32 + b;
                int j2 = base + (i + 2) * 32 + b;
                int j3 = base + (i + 3) * 32 + b;
                float4 r0 = __ldcg(&hsrc4[j0]);
                float4 r1 = __ldcg(&hsrc4[j1]);
                float4 r2 = __ldcg(&hsrc4[j2]);
                float4 r3 = __ldcg(&hsrc4[j3]);
                hsf4[j0] = r0; hsf4[j1] = r1; hsf4[j2] = r2; hsf4[j3] = r3;
            }
        }
        __syncwarp();

        // ---- compute: 64 k, 16 FMAs each (4 cols x 4 gates), h read ONCE ----
        unsigned long long a0 = 0, a1 = 0, a2 = 0, a3 = 0;
        unsigned long long a4 = 0, a5 = 0, a6 = 0, a7 = 0;
        {
            const float* hp = hs + (size_t)w * KW * 32 + b;
            const ulonglong2* wp = (const ulonglong2*)(Wsu + (size_t)w * KW * 8);
#pragma unroll 4
            for (int kk = 0; kk < KW; kk++) {
                float hv = hp[kk * 32];
                unsigned long long hh = pack2(hv, hv);
                ulonglong2 w01 = wp[kk * 4 + 0];
                ulonglong2 w23 = wp[kk * 4 + 1];
                ulonglong2 w45 = wp[kk * 4 + 2];
                ulonglong2 w67 = wp[kk * 4 + 3];
                a0 = fma2(hh, w01.x, a0); a1 = fma2(hh, w01.y, a1);
                a2 = fma2(hh, w23.x, a2); a3 = fma2(hh, w23.y, a3);
                a4 = fma2(hh, w45.x, a4); a5 = fma2(hh, w45.y, a5);
                a6 = fma2(hh, w67.x, a6); a7 = fma2(hh, w67.y, a7);
            }
        }

        // ---- publish partials: red[j][w][b] (conflict-free) ----
        red[0 * 256 + w * 32 + b] = a0;
        red[1 * 256 + w * 32 + b] = a1;
        red[2 * 256 + w * 32 + b] = a2;
        red[3 * 256 + w * 32 + b] = a3;
        red[4 * 256 + w * 32 + b] = a4;
        red[5 * 256 + w * 32 + b] = a5;
        red[6 * 256 + w * 32 + b] = a6;
        red[7 * 256 + w * 32 + b] = a7;
        __syncthreads();

        // ---- reduce + gates (epilogue threads, col nl / batch bb) ----
        if (tid < 128) {
            const unsigned long long* rif = red + (nl * 2 + 0) * 256 + bb;
            const unsigned long long* rgo = red + (nl * 2 + 1) * 256 + bb;
            unsigned long long aif = pack2(z0, z1);
            unsigned long long ago = pack2(z2, z3);
#pragma unroll
            for (int ww = 0; ww < 8; ww++) {
                aif = add2(aif, rif[ww * 32]);
                ago = add2(ago, rgo[ww * 32]);
            }
            float2 zif = unpack2(aif);
            float2 zgo = unpack2(ago);

            float ig = 1.f / (1.f + __expf(-zif.x));
            float fg = 1.f / (1.f + __expf(-zif.y));
            float gg = tanhf(zgo.x);
            float og = 1.f / (1.f + __expf(-zgo.y));
            c = fg * c + ig * gg;
            float h = og * tanhf(c);

            __stcg(&hdst[ncol * B_ + bb], h);    // publish via L2 (coalesced)
            hout[bb * 4 + nl] = h;

            if (t == T_ - 1) {
                c_fin[bb * H_ + ncol] = c;
                h_fin[bb * H_ + ncol] = h;
            }
        }
        __syncthreads();

        // ---- coalesced history write: one STG.128 per batch row ----
        if (tid < 32) {
            float4 hv4 = ((const float4*)hout)[tid];
            *(float4*)&hist[((size_t)tid * T_ + t) * H_ + blockIdx.x * 4] = hv4;
        }

        // ---- monotonic hierarchical grid barrier ----
        __threadfence();              // order h publish before arrive
        __syncthreads();              // all lanes done with hs/red, too
        if (tid == 0) {
            unsigned target = (unsigned)(t + 1);
            unsigned old = atomicAdd(&g_grp[grp * 32], 1);
            if (old == 8u * target - 1u) {
                unsigned r = atomicAdd(&g_root, 1);
                if (r == 16u * target - 1u) g_sense = target;
            }
            while (g_sense < target) { }
        }
        __syncthreads();
        // no consumer threadfence: cross-step reads bypass L1 (.cg/.volatile)
    }
}

// ---------------- launch ----------------
extern "C" void kernel_launch(void* const* d_in, const int* in_sizes, int n_in,
                              void* d_out, int out_size) {
    const float* x    = (const float*)d_in[0];
    const float* h0   = (const float*)d_in[1];
    const float* c0   = (const float*)d_in[2];
    const float* Wh   = (const float*)d_in[4];
    const float* Wi   = (const float*)d_in[3];
    const float* bias = (const float*)d_in[5];
    float* out = (float*)d_out;

    // 32KB (Wsu) + 64KB (hs) + 16KB (red) + 512B (hout)
    const int rec_smem = 512 * 8 * 8 + 512 * 32 * 4 + 8 * 8 * 32 * 8 + 128 * 4;
    cudaFuncSetAttribute(lstm_rec, cudaFuncAttributeMaxDynamicSharedMemorySize,
                         rec_smem);

    dim3 ggrid(G4H / 64, (B_ * T_) / 64);
    gemm_xwi<<<ggrid, 256>>>(x, Wi, bias, h0);

    lstm_rec<<<NB, NT, rec_smem>>>(c0, Wh, out);
}